// round 5
// baseline (speedup 1.0000x reference)
#include <cuda_runtime.h>
#include <cuda_bf16.h>
#include <cstdint>

#define MROWS 50176          // 256 * 196
#define DDIM  384
#define HDIM  1536
#define NOUT  (MROWS * DDIM)

// ---------------------------------------------------------------------------
// Scratch (device globals). Total ~98 MB.
// ---------------------------------------------------------------------------
__device__ __align__(256) signed char g_xq[(size_t)MROWS * DDIM];   // x as s8
__device__ __align__(256) signed char g_hq[(size_t)MROWS * HDIM];   // quantized h as s8
__device__ __align__(256) signed char g_w1q[(size_t)HDIM * DDIM];
__device__ __align__(256) signed char g_w2q[(size_t)DDIM * HDIM];
__device__ float g_scale1[HDIM];
__device__ int   g_bint1[HDIM];
__device__ float g_w2sf[DDIM];
__device__ float g_scale2[DDIM];
__device__ int   g_bint2[DDIM];
__device__ unsigned g_max1, g_max2;
__device__ float g_sf1, g_inv_sf1, g_sf2, g_inv_sf2;

__device__ __forceinline__ float clamp8(float v) {
    return fminf(127.0f, fmaxf(-128.0f, v));
}

// ---------------------------------------------------------------------------
// PTX helpers
// ---------------------------------------------------------------------------
__device__ __forceinline__ void cp16(uint32_t dst, const void* src) {
    asm volatile("cp.async.cg.shared.global [%0], [%1], 16;" :: "r"(dst), "l"(src) : "memory");
}
__device__ __forceinline__ void cp_commit() {
    asm volatile("cp.async.commit_group;" ::: "memory");
}
__device__ __forceinline__ void ldsm4(uint32_t* r, uint32_t addr) {
    asm volatile("ldmatrix.sync.aligned.m8n8.x4.shared.b16 {%0,%1,%2,%3}, [%4];"
                 : "=r"(r[0]), "=r"(r[1]), "=r"(r[2]), "=r"(r[3]) : "r"(addr));
}
__device__ __forceinline__ void imma16832(int c[4],
                                          uint32_t a0, uint32_t a1, uint32_t a2, uint32_t a3,
                                          uint32_t b0, uint32_t b1) {
    asm volatile(
        "mma.sync.aligned.m16n8k32.row.col.s32.s8.s8.s32 "
        "{%0,%1,%2,%3}, {%4,%5,%6,%7}, {%8,%9}, {%0,%1,%2,%3};\n"
        : "+r"(c[0]), "+r"(c[1]), "+r"(c[2]), "+r"(c[3])
        : "r"(a0), "r"(a1), "r"(a2), "r"(a3), "r"(b0), "r"(b1));
}

// ---------------------------------------------------------------------------
// Small kernels (unchanged — proven)
// ---------------------------------------------------------------------------
__global__ void k_init() { g_max1 = 0u; g_max2 = 0u; }

__global__ void k_quant_w1(const float* __restrict__ W, const float* __restrict__ b,
                           const float* __restrict__ asf) {
    int o = blockIdx.x;
    const float* row = W + (size_t)o * DDIM;
    float m = 0.0f;
    for (int d = threadIdx.x; d < DDIM; d += blockDim.x) m = fmaxf(m, fabsf(row[d]));
    for (int off = 16; off; off >>= 1) m = fmaxf(m, __shfl_xor_sync(0xffffffffu, m, off));
    __shared__ float sred[8]; __shared__ float s_sf;
    int wid = threadIdx.x >> 5;
    if ((threadIdx.x & 31) == 0) sred[wid] = m;
    __syncthreads();
    if (threadIdx.x == 0) {
        float mm = sred[0];
        for (int i = 1; i < (int)(blockDim.x >> 5); i++) mm = fmaxf(mm, sred[i]);
        float sf = __fdiv_rn(mm, 127.0f);
        s_sf = sf;
        float sc = sf * asf[0];
        g_scale1[o] = sc;
        g_bint1[o]  = __float2int_rn(__fdiv_rn(b[o], sc));
    }
    __syncthreads();
    float sf = s_sf;
    for (int d = threadIdx.x; d < DDIM; d += blockDim.x) {
        g_w1q[(size_t)o * DDIM + d] = (signed char)(int)clamp8(rintf(__fdiv_rn(row[d], sf)));
    }
}

__global__ void k_quant_w2(const float* __restrict__ W) {
    int o = blockIdx.x;
    const float* row = W + (size_t)o * HDIM;
    float m = 0.0f;
    for (int d = threadIdx.x; d < HDIM; d += blockDim.x) m = fmaxf(m, fabsf(row[d]));
    for (int off = 16; off; off >>= 1) m = fmaxf(m, __shfl_xor_sync(0xffffffffu, m, off));
    __shared__ float sred[8]; __shared__ float s_sf;
    int wid = threadIdx.x >> 5;
    if ((threadIdx.x & 31) == 0) sred[wid] = m;
    __syncthreads();
    if (threadIdx.x == 0) {
        float mm = sred[0];
        for (int i = 1; i < (int)(blockDim.x >> 5); i++) mm = fmaxf(mm, sred[i]);
        float sf = __fdiv_rn(mm, 127.0f);
        s_sf = sf;
        g_w2sf[o] = sf;
    }
    __syncthreads();
    float sf = s_sf;
    for (int d = threadIdx.x; d < HDIM; d += blockDim.x) {
        g_w2q[(size_t)o * HDIM + d] = (signed char)(int)clamp8(rintf(__fdiv_rn(row[d], sf)));
    }
}

__global__ void k_quant_x(const float4* __restrict__ x4, const float* __restrict__ asf) {
    int i = blockIdx.x * blockDim.x + threadIdx.x;
    float inv = __frcp_rn(asf[0]);
    float4 v = x4[i];
    int q0 = (int)clamp8(rintf(v.x * inv));
    int q1 = (int)clamp8(rintf(v.y * inv));
    int q2 = (int)clamp8(rintf(v.z * inv));
    int q3 = (int)clamp8(rintf(v.w * inv));
    uint32_t p = (uint32_t)(q0 & 0xFF) | ((uint32_t)(q1 & 0xFF) << 8)
               | ((uint32_t)(q2 & 0xFF) << 16) | ((uint32_t)(q3 & 0xFF) << 24);
    reinterpret_cast<uint32_t*>(g_xq)[i] = p;
}

__global__ void k_scale2(const float* __restrict__ b2) {
    int o = threadIdx.x;
    float sf1 = __fdiv_rn(__uint_as_float(g_max1), 127.0f);
    if (o == 0) { g_sf1 = sf1; g_inv_sf1 = __fdiv_rn(1.0f, sf1); }
    float sc = g_w2sf[o] * sf1;
    g_scale2[o] = sc;
    g_bint2[o]  = __float2int_rn(__fdiv_rn(b2[o], sc));
}

__global__ void k_sf2(float* __restrict__ out, int writeExtra) {
    float sf2 = __fdiv_rn(__uint_as_float(g_max2), 127.0f);
    g_sf2 = sf2;
    g_inv_sf2 = __fdiv_rn(1.0f, sf2);
    if (writeExtra) out[NOUT] = sf2;
}

__global__ void k_requant(float4* __restrict__ y) {
    int i = blockIdx.x * blockDim.x + threadIdx.x;
    float s = g_sf2, inv = g_inv_sf2;
    float4 v = y[i];
    v.x = clamp8(rintf(v.x * inv)) * s;
    v.y = clamp8(rintf(v.y * inv)) * s;
    v.z = clamp8(rintf(v.z * inv)) * s;
    v.w = clamp8(rintf(v.w * inv)) * s;
    y[i] = v;
}

// ---------------------------------------------------------------------------
// GEMM: s8 IMMA, CTA tile 256(M) x 128(N), 8 warps (4m x 2n), warp tile 64x64.
// K-slab = 128 s8 bytes; 3-stage cp.async ring; ldmatrix feeds.
// Swizzle: 16B-chunk' = chunk ^ (row & 7); rows are 128 B.
// EPI=0: gemm1 pass A -> max(relu(h)) only
// EPI=1: gemm1 pass B -> write quantized h (s8)
// EPI=2: gemm2       -> write y fp32 + max|y|
// ---------------------------------------------------------------------------
#define STAGES 3
#define A_BYTES 32768                  // 256 rows x 128 B
#define B_BYTES 16384                  // 128 rows x 128 B
#define GEMM_SMEM (STAGES * (A_BYTES + B_BYTES) + 1024)

template<int KBYTES, int EPI>
__global__ void __launch_bounds__(256, 1) k_gemm(float* __restrict__ Y) {
    extern __shared__ char smem[];
    __shared__ float s_scale[128];
    __shared__ int   s_bint[128];
    __shared__ float s_red[8];

    const uint32_t sbase = (uint32_t)__cvta_generic_to_shared(smem);
    const uint32_t dataBase = (sbase + 1023u) & ~1023u;
    const int tid = threadIdx.x;
    const int wid = tid >> 5, lane = tid & 31;
    const int bx = blockIdx.x, by = blockIdx.y;
    const int warp_m = wid & 3, warp_n = wid >> 2;

    const signed char* Aptr = (EPI == 2) ? g_hq  : g_xq;
    const signed char* Bptr = (EPI == 2) ? g_w2q : g_w1q;
    const float* SC = (EPI == 2) ? g_scale2 : g_scale1;
    const int*   BI = (EPI == 2) ? g_bint2  : g_bint1;

    if (tid < 128) s_scale[tid] = SC[bx * 128 + tid];
    else           s_bint[tid - 128] = BI[bx * 128 + tid - 128];

    const char* Abase = (const char*)Aptr + (size_t)by * 256 * KBYTES;
    const char* Bbase = (const char*)Bptr + (size_t)bx * 128 * KBYTES;

    auto load_tile = [&](int kt, int s) {
        uint32_t da = dataBase + s * A_BYTES;
        uint32_t db = dataBase + STAGES * A_BYTES + s * B_BYTES;
        size_t koff = (size_t)kt * 128;
#pragma unroll
        for (int it = 0; it < 8; it++) {      // A: 256 rows x 8 chunks = 2048
            int idx = tid + it * 256;
            int row = idx >> 3, j = idx & 7;
            uint32_t so = (uint32_t)(row * 128) + (uint32_t)((j ^ (row & 7)) << 4);
            cp16(da + so, Abase + (size_t)row * KBYTES + koff + j * 16);
        }
#pragma unroll
        for (int it = 0; it < 4; it++) {      // B: 128 rows x 8 chunks = 1024
            int idx = tid + it * 256;
            int row = idx >> 3, j = idx & 7;
            uint32_t so = (uint32_t)(row * 128) + (uint32_t)((j ^ (row & 7)) << 4);
            cp16(db + so, Bbase + (size_t)row * KBYTES + koff + j * 16);
        }
        cp_commit();
    };

    int acc[4][8][4];
#pragma unroll
    for (int a = 0; a < 4; a++)
#pragma unroll
        for (int b = 0; b < 8; b++)
#pragma unroll
            for (int c = 0; c < 4; c++) acc[a][b][c] = 0;

    constexpr int KT = KBYTES / 128;
    load_tile(0, 0);
    if (KT > 1) load_tile(1, 1);

    for (int kt = 0; kt < KT; kt++) {
        if (kt == KT - 1) asm volatile("cp.async.wait_group 0;" ::: "memory");
        else              asm volatile("cp.async.wait_group 1;" ::: "memory");
        __syncthreads();
        if (kt + 2 < KT) load_tile(kt + 2, (kt + 2) % STAGES);

        uint32_t sa = dataBase + (kt % STAGES) * A_BYTES;
        uint32_t sb = dataBase + STAGES * A_BYTES + (kt % STAGES) * B_BYTES;
#pragma unroll
        for (int ks = 0; ks < 4; ks++) {         // 4 x k32 per 128-B slab
            int c0 = 2 * ks;
            uint32_t afr[4][4];
#pragma unroll
            for (int mt = 0; mt < 4; mt++) {
                int row = warp_m * 64 + mt * 16 + (lane & 15);
                int ch = c0 + (lane >> 4);
                ldsm4(afr[mt], sa + (uint32_t)(row * 128) + (uint32_t)((ch ^ (row & 7)) << 4));
            }
            uint32_t bfr[4][4];
#pragma unroll
            for (int nb = 0; nb < 4; nb++) {
                int row = warp_n * 64 + nb * 16 + (lane & 7) + ((lane >> 4) << 3);
                int ch = c0 + ((lane >> 3) & 1);
                ldsm4(bfr[nb], sb + (uint32_t)(row * 128) + (uint32_t)((ch ^ (row & 7)) << 4));
            }
#pragma unroll
            for (int mt = 0; mt < 4; mt++)
#pragma unroll
                for (int nt = 0; nt < 8; nt++)
                    imma16832(acc[mt][nt],
                              afr[mt][0], afr[mt][1], afr[mt][2], afr[mt][3],
                              bfr[nt >> 1][(nt & 1) * 2], bfr[nt >> 1][(nt & 1) * 2 + 1]);
        }
    }

    // ------------------------- epilogue -------------------------
    int g  = lane >> 2, tg = lane & 3;
    float lmax = 0.0f;
    const int rowbase = by * 256 + warp_m * 64;
    float inv1 = (EPI == 1) ? g_inv_sf1 : 0.0f;
#pragma unroll
    for (int nt = 0; nt < 8; nt++) {
        int cl = warp_n * 64 + nt * 8 + 2 * tg;
        int cglob = bx * 128 + cl;
        float s0 = s_scale[cl],  s1 = s_scale[cl + 1];
        int  bi0 = s_bint[cl],   bi1 = s_bint[cl + 1];
#pragma unroll
        for (int mt = 0; mt < 4; mt++) {
            int r = rowbase + mt * 16 + g;
            float v0 = __int2float_rn(acc[mt][nt][0] + bi0) * s0;
            float v1 = __int2float_rn(acc[mt][nt][1] + bi1) * s1;
            float v2 = __int2float_rn(acc[mt][nt][2] + bi0) * s0;
            float v3 = __int2float_rn(acc[mt][nt][3] + bi1) * s1;
            if (EPI == 0) {
                v0 = fmaxf(v0, 0.0f); v1 = fmaxf(v1, 0.0f);
                v2 = fmaxf(v2, 0.0f); v3 = fmaxf(v3, 0.0f);
                lmax = fmaxf(lmax, fmaxf(fmaxf(v0, v1), fmaxf(v2, v3)));
            } else if (EPI == 1) {
                v0 = fmaxf(v0, 0.0f); v1 = fmaxf(v1, 0.0f);
                v2 = fmaxf(v2, 0.0f); v3 = fmaxf(v3, 0.0f);
                int q0 = (int)clamp8(rintf(v0 * inv1));
                int q1 = (int)clamp8(rintf(v1 * inv1));
                int q2 = (int)clamp8(rintf(v2 * inv1));
                int q3 = (int)clamp8(rintf(v3 * inv1));
                *reinterpret_cast<short*>(g_hq + (size_t)r * HDIM + cglob) =
                    (short)((q0 & 0xFF) | ((q1 & 0xFF) << 8));
                *reinterpret_cast<short*>(g_hq + (size_t)(r + 8) * HDIM + cglob) =
                    (short)((q2 & 0xFF) | ((q3 & 0xFF) << 8));
            } else {
                lmax = fmaxf(lmax, fmaxf(fmaxf(fabsf(v0), fabsf(v1)),
                                          fmaxf(fabsf(v2), fabsf(v3))));
                *reinterpret_cast<float2*>(&Y[(size_t)r * DDIM + cglob])       = make_float2(v0, v1);
                *reinterpret_cast<float2*>(&Y[(size_t)(r + 8) * DDIM + cglob]) = make_float2(v2, v3);
            }
        }
    }
    if (EPI != 1) {
        for (int off = 16; off; off >>= 1) lmax = fmaxf(lmax, __shfl_xor_sync(0xffffffffu, lmax, off));
        if (lane == 0) s_red[wid] = lmax;
        __syncthreads();
        if (tid == 0) {
            float m = s_red[0];
#pragma unroll
            for (int i = 1; i < 8; i++) m = fmaxf(m, s_red[i]);
            atomicMax(EPI == 0 ? &g_max1 : &g_max2, __float_as_uint(m));
        }
    }
}

// ---------------------------------------------------------------------------
// Launch
// ---------------------------------------------------------------------------
extern "C" void kernel_launch(void* const* d_in, const int* in_sizes, int n_in,
                              void* d_out, int out_size) {
    (void)in_sizes; (void)n_in;
    const float* x   = (const float*)d_in[0];
    const float* W1  = (const float*)d_in[1];
    const float* b1  = (const float*)d_in[2];
    const float* W2  = (const float*)d_in[3];
    const float* b2  = (const float*)d_in[4];
    const float* asf = (const float*)d_in[5];
    float* y = (float*)d_out;

    cudaFuncSetAttribute(k_gemm<DDIM, 0>, cudaFuncAttributeMaxDynamicSharedMemorySize, GEMM_SMEM);
    cudaFuncSetAttribute(k_gemm<DDIM, 1>, cudaFuncAttributeMaxDynamicSharedMemorySize, GEMM_SMEM);
    cudaFuncSetAttribute(k_gemm<HDIM, 2>, cudaFuncAttributeMaxDynamicSharedMemorySize, GEMM_SMEM);

    k_init<<<1, 1>>>();
    k_quant_w1<<<HDIM, 128>>>(W1, b1, asf);
    k_quant_w2<<<DDIM, 256>>>(W2);
    k_quant_x<<<(NOUT / 4) / 256, 256>>>((const float4*)x, asf);

    dim3 g1(HDIM / 128, MROWS / 256);   // 12 x 196
    dim3 g2(DDIM / 128, MROWS / 256);   // 3  x 196
    k_gemm<DDIM, 0><<<g1, 256, GEMM_SMEM>>>(y);   // max(relu(h)) only
    k_scale2<<<1, DDIM>>>(b2);
    k_gemm<DDIM, 1><<<g1, 256, GEMM_SMEM>>>(y);   // write quantized h (s8)
    k_gemm<HDIM, 2><<<g2, 256, GEMM_SMEM>>>(y);   // y fp32 + max|y|
    k_sf2<<<1, 1>>>(y, (out_size > NOUT) ? 1 : 0);
    k_requant<<<(NOUT / 4) / 256, 256>>>((float4*)y);
}